// round 13
// baseline (speedup 1.0000x reference)
#include <cuda_runtime.h>

#define DT 0.005f

// ---------------- scratch (no allocation allowed) ----------------
__device__ float    g_partials[4096];
__device__ unsigned g_sem = 0;
__device__ float4   g_coef[8192];   // fallback path only

// fallback float2 swizzle
__device__ __forceinline__ int swz(int t)  { return t ^ ((t >> 4) & 15); }
// float4 swizzle
__device__ __forceinline__ int swz4(int s) { return s ^ ((s >> 3) & 7); }

__device__ __forceinline__ void cp16(unsigned dst, const void* src) {
    asm volatile("cp.async.cg.shared.global [%0], [%1], 16;\n" :: "r"(dst), "l"(src));
}
__device__ __forceinline__ void cp_commit() { asm volatile("cp.async.commit_group;\n"); }
template <int N>
__device__ __forceinline__ void cp_wait() { asm volatile("cp.async.wait_group %0;\n" :: "n"(N)); }

// ============================================================================
// Row-pipelined scan kernel. One CTA per row (grid B=512), 256 thr.
// The row is processed as TWO half-tiles (2048 steps each, CHUNK=8) with
// double-buffered cp.async: both buffers are issued at t=0, so buf1's DRAM
// transfer overlaps ALL of half0's compute — the stage-wait is paid once.
// The scan carry crosses halves EXACTLY (fold of the 8 warp partials gives
// v_end -> v_init of half1): no halo loads, no halo dot product.
// Pass2-free algebra (proven R10/R11): pass1 writes Ploc = kp*z + dkp*v_loc
// in place; pass3 rebuilds P = Ploc + dkp*g^(2*(j&3)) * v_e.
// Transient t<64 handled exactly by threads j<8 of half0 via gain table.
// ============================================================================
__global__ void __launch_bounds__(256, 6)
kf_row(const float* __restrict__ pred, const float* __restrict__ targ,
       const float* __restrict__ qv_p, const float* __restrict__ r_p,
       float* __restrict__ out, int B)
{
    constexpr int NT    = 256;
    constexpr int CHUNK = 8;
    constexpr int NPAIR = 1024;          // pairs per half (2048 timesteps)
    constexpr int TTR   = 64;            // transient length (conv ~1e-10 by 64)
    constexpr int NTC   = TTR / CHUNK;   // 8 transient chunks

    __shared__ float4 sbuf[2][NPAIR];    // double-buffered pred -> Ploc/P
    __shared__ float4 s_tc[TTR];         // transient (g, kv, u, inv)
    __shared__ float2 s_tb[NTC];         // per-chunk b-affine (Gb, Hb)
    __shared__ float2 s_ve[NT];          // per-chunk entry state v_e
    __shared__ float2 s_vnext;           // exact carry: v at end of half 0
    __shared__ float  sWG[8], sWBx[8], sWBy[8];
    __shared__ float  sred[8];
    __shared__ float  sf[NT];
    __shared__ int    s_last;

    const int j    = threadIdx.x;
    const int row  = blockIdx.x;
    const int lane = j & 31;
    const int wrp  = j >> 5;

    const float qv = __ldg(qv_p);
    const float r  = __ldg(r_p);

    const unsigned sa0 = (unsigned)__cvta_generic_to_shared(&sbuf[0][0]);
    const unsigned sa1 = (unsigned)__cvta_generic_to_shared(&sbuf[1][0]);

    // ---- issue BOTH half-tiles immediately (double buffer) ----
    const float4* gp4 = (const float4*)pred + (size_t)row * 2048;
    #pragma unroll
    for (int k = 0; k < 4; ++k) {
        int m = j + k * NT;
        cp16(sa0 + 16u * (unsigned)swz4(m), gp4 + m);
    }
    cp_commit();                                  // group: buf0
    #pragma unroll
    for (int k = 0; k < 4; ++k) {
        int m = j + k * NT;
        cp16(sa1 + 16u * (unsigned)swz4(m), gp4 + NPAIR + m);
    }
    cp_commit();                                  // group: buf1

    // ---- steady-state constants, per-thread ----
    const float cstar = 0.5f * (sqrtf(fmaf(qv, qv, 4.f * r * qv)) - qv);
    const float cps   = cstar + qv;
    const float invs  = 1.0f / (cps + r);
    const float kvs   = cps * invs;
    const float gs    = 1.0f - kvs;
    const float us    = DT * cstar * invs;
    const float kps   = us / kvs;                 // kp* = u*/(1-g*)
    const float dkp   = DT - kps;
    const float gg2 = gs * gs, gg4 = gg2 * gg2;
    const float gg8 = gg4 * gg4;                  // g^CHUNK

    // ---- transient gain table + per-chunk b-affine (j < 8) ----
    if (j < NTC) {
        const float r64   = 64.f * r;
        const float rqv64 = 64.f * r * qv;
        const float qvr   = qv + r;
        const float qvr64 = 64.f * qvr;
        const int tstart  = j * CHUNK;
        float p = 1.f, q = 1.f;                   // c0 = 1
        #pragma unroll 1
        for (int s = 0; s < tstart; ++s) {
            float pn = fmaf(r64, p, rqv64 * q);
            float qn = fmaf(qvr64, q, 64.f * p);
            p = pn; q = qn;
        }
        float Gb = 1.f, Hb = 0.f;                 // b' = g*b + r*u
        #pragma unroll 1
        for (int i = 0; i < CHUNK; ++i) {
            float num  = fmaf(qv,  q, p);
            float den  = fmaf(qvr, q, p);
            float invd = 1.0f / den;
            float kv   = num * invd;
            float inv  = q * invd;
            float u    = DT * p * invd;
            float g    = 1.0f - kv;
            s_tc[tstart + i] = make_float4(g, kv, u, inv);
            Hb = fmaf(g, Hb, r * u);
            Gb *= g;
            float pn = fmaf(r64, p, rqv64 * q);
            float qn = fmaf(qvr64, q, 64.f * p);
            p = pn; q = qn;
        }
        s_tb[j] = make_float2(Gb, Hb);
    }

    // per-thread pass3 weights (local pair index j&3 is k-invariant)
    const int   lpi = j & 3;
    float gpow = 1.f;
    if (lpi == 1) gpow = gg2;
    else if (lpi == 2) gpow = gg4;
    else if (lpi == 3) gpow = gg4 * gg2;
    const float w0 = dkp * gpow;
    const float w1 = w0 * gs;

    float acc = 0.f;

    #pragma unroll
    for (int half = 0; half < 2; ++half) {
        float4* sz = sbuf[half];
        if (half == 0) cp_wait<1>(); else cp_wait<0>();
        __syncthreads();                          // data (+tables) ready;
                                                  // also orders prev pass3 reads
        const bool trans = (half == 0) && (j < NTC);
        const int  p0 = 4 * j;                    // first local pair of chunk

        // v at half entry (exact)
        float vix = 0.f, viy = 0.f;
        if (half == 1) { float2 vn = s_vnext; vix = vn.x; viy = vn.y; }

        // ---- pass 1: local v-affine; steady threads emit Ploc in place ----
        float G, Bx = 0.f, By = 0.f;
        if (trans) {
            G = 1.f;
            const int t0 = j * CHUNK;
            #pragma unroll
            for (int i = 0; i < 4; ++i) {
                float4 Z  = sz[swz4(p0 + i)];
                float4 c0 = s_tc[t0 + 2 * i];
                float4 c1 = s_tc[t0 + 2 * i + 1];
                Bx = fmaf(c0.x, Bx, c0.y * Z.x);
                By = fmaf(c0.x, By, c0.y * Z.y);
                Bx = fmaf(c1.x, Bx, c1.y * Z.z);
                By = fmaf(c1.x, By, c1.y * Z.w);
                G *= c0.x * c1.x;
            }
        } else {
            G = gg8;
            #pragma unroll
            for (int i = 0; i < 4; ++i) {
                float4 Z = sz[swz4(p0 + i)];
                float P0x = fmaf(kps, Z.x, dkp * Bx);   // v_loc BEFORE step
                float P0y = fmaf(kps, Z.y, dkp * By);
                Bx = fmaf(gs, Bx, kvs * Z.x);
                By = fmaf(gs, By, kvs * Z.y);
                float P1x = fmaf(kps, Z.z, dkp * Bx);
                float P1y = fmaf(kps, Z.w, dkp * By);
                Bx = fmaf(gs, Bx, kvs * Z.z);
                By = fmaf(gs, By, kvs * Z.w);
                sz[swz4(p0 + i)] = make_float4(P0x, P0y, P1x, P1y);
            }
        }

        // ---- 3-component scan: intra-warp inclusive + warp fold ----
        #pragma unroll
        for (int off = 1; off < 32; off <<= 1) {
            float pG  = __shfl_up_sync(0xffffffffu, G,  off);
            float pBx = __shfl_up_sync(0xffffffffu, Bx, off);
            float pBy = __shfl_up_sync(0xffffffffu, By, off);
            if (lane >= off) {
                Bx = fmaf(G, pBx, Bx);
                By = fmaf(G, pBy, By);
                G *= pG;
            }
        }
        float eG  = __shfl_up_sync(0xffffffffu, G,  1);
        float eBx = __shfl_up_sync(0xffffffffu, Bx, 1);
        float eBy = __shfl_up_sync(0xffffffffu, By, 1);
        if (lane == 0) { eG = 1.f; eBx = 0.f; eBy = 0.f; }
        if (lane == 31) { sWG[wrp] = G; sWBx[wrp] = Bx; sWBy[wrp] = By; }
        __syncthreads();                          // [B] warp partials ready

        float Gp = 1.f, Bpx = 0.f, Bpy = 0.f;
        #pragma unroll
        for (int k = 0; k < 7; ++k) {
            if (k < wrp) {
                Bpx = fmaf(sWG[k], Bpx, sWBx[k]);
                Bpy = fmaf(sWG[k], Bpy, sWBy[k]);
                Gp *= sWG[k];
            }
        }
        float Ge = eG * Gp;
        float vx = fmaf(Ge, vix, fmaf(eG, Bpx, eBx));  // v at chunk entry
        float vy = fmaf(Ge, viy, fmaf(eG, Bpy, eBy));

        // exact carry to next half (thread 0 folds all 8 warp partials)
        if (half == 0 && j == 0) {
            float Gt = 1.f, Bxt = 0.f, Byt = 0.f;
            #pragma unroll
            for (int k = 0; k < 8; ++k) {
                Bxt = fmaf(sWG[k], Bxt, sWBx[k]);
                Byt = fmaf(sWG[k], Byt, sWBy[k]);
                Gt *= sWG[k];
            }
            s_vnext = make_float2(fmaf(Gt, vix, Bxt), fmaf(Gt, viy, Byt));
        }

        // ---- publish entry state; transient does exact replay (writes P) ----
        if (trans) {
            s_ve[j] = make_float2(0.f, 0.f);
            float b = 0.f;
            #pragma unroll
            for (int k = 0; k < NTC - 1; ++k) {
                if (k < j) { float2 tb = s_tb[k]; b = fmaf(tb.x, b, tb.y); }
            }
            const int t0 = j * CHUNK;
            #pragma unroll 1
            for (int i = 0; i < 4; ++i) {
                float4 Z  = sz[swz4(p0 + i)];
                float4 c0 = s_tc[t0 + 2 * i];
                float4 c1 = s_tc[t0 + 2 * i + 1];
                float kp0 = fmaf(b, c0.w, c0.z);  b = r * kp0;
                float dx0 = Z.x - vx, dy0 = Z.y - vy;
                float Px0 = fmaf(kp0, dx0, DT * vx);
                float Py0 = fmaf(kp0, dy0, DT * vy);
                vx = fmaf(c0.y, dx0, vx); vy = fmaf(c0.y, dy0, vy);
                float kp1 = fmaf(b, c1.w, c1.z);  b = r * kp1;
                float dx1 = Z.z - vx, dy1 = Z.w - vy;
                float Px1 = fmaf(kp1, dx1, DT * vx);
                float Py1 = fmaf(kp1, dy1, DT * vy);
                vx = fmaf(c1.y, dx1, vx); vy = fmaf(c1.y, dy1, vy);
                sz[swz4(p0 + i)] = make_float4(Px0, Py0, Px1, Py1);
            }
        } else {
            s_ve[j] = make_float2(vx, vy);
        }
        __syncthreads();                          // [C] P/Ploc + v_e ready

        // ---- pass 3: coalesced targ; P = Ploc + w*v_e; loss ----
        const float4* gt = (const float4*)targ + (size_t)row * 2048
                         + (size_t)half * NPAIR;
        #pragma unroll
        for (int k = 0; k < 4; ++k) {
            int m = j + k * NT;
            float4 W  = gt[m];
            float4 P  = sz[swz4(m)];
            float2 ve = s_ve[(j >> 2) + k * 64];
            float Px0 = fmaf(w0, ve.x, P.x);
            float Py0 = fmaf(w0, ve.y, P.y);
            float Px1 = fmaf(w1, ve.x, P.z);
            float Py1 = fmaf(w1, ve.y, P.w);
            if (half != 0 || m != 0) {            // t = 0 has no loss term
                float ex = fmaf(-DT, W.x, Px0);
                float ey = fmaf(-DT, W.y, Py0);
                acc = fmaf(ex, ex, fmaf(ey, ey, acc));
            }
            float ex1 = fmaf(-DT, W.z, Px1);
            float ey1 = fmaf(-DT, W.w, Py1);
            acc = fmaf(ex1, ex1, fmaf(ey1, ey1, acc));
        }
    }

    // ---- block reduce -> partial ----
    #pragma unroll
    for (int o = 16; o; o >>= 1) acc += __shfl_down_sync(0xffffffffu, acc, o);
    if (lane == 0) sred[wrp] = acc;
    __syncthreads();
    if (j == 0) {
        float v = 0.f;
        #pragma unroll
        for (int k = 0; k < 8; ++k) v += sred[k];
        g_partials[row] = v;
        __threadfence();
        unsigned done = atomicAdd(&g_sem, 1u);
        s_last = (done == (unsigned)gridDim.x - 1u);
    }
    __syncthreads();

    // ---- last CTA: deterministic final reduction + semaphore reset ----
    if (s_last) {
        __threadfence();
        float v = 0.f;
        for (int i = j; i < B; i += NT) v += g_partials[i];
        sf[j] = v;
        __syncthreads();
        for (int o = 128; o; o >>= 1) {
            if (j < o) sf[j] += sf[j + o];
            __syncthreads();
        }
        if (j == 0) {
            out[0] = sf[0] / ((float)B * 4095.0f * 2.f);
            atomicExch(&g_sem, 0u);
        }
    }
}

// ============================================================================
// Fallback path (any T) — proven Round-1 kernels
// ============================================================================
__global__ void kf_setup(const float* __restrict__ q_vel_p,
                         const float* __restrict__ r_vel_p, int T) {
    __shared__ float skp[4096];
    __shared__ float skv[4096];
    __shared__ int   s_conv;
    __shared__ float s_kp_last, s_kv_last;

    int Tser = T < 4096 ? T : 4096;
    if (threadIdx.x == 0) {
        float qvv = *q_vel_p;
        float rr  = *r_vel_p;
        float bb = 0.f, cc = 1.f;
        float kp = 0.f, kv = 0.f;
        int tconv = Tser;
        for (int t = 0; t < Tser; ++t) {
            float cp  = cc + qvv;
            float bp  = fmaf(DT, cc, bb);
            float S   = cp + rr;
            float inv = __fdividef(1.f, S);
            kv = cp * inv;
            kp = bp * inv;
            skp[t] = kp; skv[t] = kv;
            float rs = rr * inv;
            float nc = cp * rs;
            float nb = bp * rs;
            if (nc == cc && nb == bb) { tconv = t + 1; break; }
            cc = nc; bb = nb;
        }
        s_conv = tconv; s_kp_last = kp; s_kv_last = kv;
    }
    __syncthreads();
    int   tconv = s_conv;
    float kpl = s_kp_last, kvl = s_kv_last;
    for (int t = threadIdx.x; t < T; t += blockDim.x) {
        float kp = (t < tconv) ? skp[t] : kpl;
        float kv = (t < tconv) ? skv[t] : kvl;
        g_coef[t] = make_float4(1.f - kv, kv, DT - kp, kp);
    }
}

__global__ void __launch_bounds__(256)
kf_main(const float* __restrict__ pred, const float* __restrict__ targ, int T) {
    extern __shared__ float2 sp2[];
    const int NT = 256;
    int j = threadIdx.x, bb = blockIdx.x;

    const float4* gp = (const float4*)(pred + (size_t)bb * T * 2);
    int n4 = (T * 2) / 4;
    for (int m = j; m < n4; m += NT) {
        float4 v = gp[m];
        sp2[swz(2 * m)]     = make_float2(v.x, v.y);
        sp2[swz(2 * m + 1)] = make_float2(v.z, v.w);
    }
    __syncthreads();

    int chunk = (T + NT - 1) / NT;
    int t0 = j * chunk;

    float A = 1.f, Bx = 0.f, By = 0.f;
    for (int i = 0; i < chunk; ++i) {
        int t = t0 + i;
        if (t >= T) break;
        float4 cf = g_coef[t];
        float2 z  = sp2[swz(t)];
        A  = A * cf.x;
        Bx = fmaf(cf.x, Bx, cf.y * z.x);
        By = fmaf(cf.x, By, cf.y * z.y);
    }

    __shared__ float sA[256], sBx[256], sBy[256];
    sA[j] = A; sBx[j] = Bx; sBy[j] = By;
    __syncthreads();
    for (int off = 1; off < NT; off <<= 1) {
        float a2 = 0.f, bx2 = 0.f, by2 = 0.f;
        bool act = (j >= off);
        if (act) {
            float ap = sA[j - off], bxp = sBx[j - off], byp = sBy[j - off];
            a2  = A * ap;
            bx2 = fmaf(A, bxp, Bx);
            by2 = fmaf(A, byp, By);
        }
        __syncthreads();
        if (act) { A = a2; Bx = bx2; By = by2; sA[j] = A; sBx[j] = Bx; sBy[j] = By; }
        __syncthreads();
    }
    float vx = (j == 0) ? 0.f : sBx[j - 1];
    float vy = (j == 0) ? 0.f : sBy[j - 1];

    const float2* gt2 = (const float2*)(targ + (size_t)bb * T * 2);
    float acc = 0.f;
    for (int i = 0; i < chunk; ++i) {
        int t = t0 + i;
        if (t >= T) break;
        float4 cf = g_coef[t];
        float2 z  = sp2[swz(t)];
        if (t > 0) {
            float2 w = gt2[t];
            float ex = fmaf(cf.z, vx, fmaf(cf.w, z.x, -DT * w.x));
            float ey = fmaf(cf.z, vy, fmaf(cf.w, z.y, -DT * w.y));
            acc = fmaf(ex, ex, fmaf(ey, ey, acc));
        }
        vx = fmaf(cf.x, vx, cf.y * z.x);
        vy = fmaf(cf.x, vy, cf.y * z.y);
    }

    for (int o = 16; o; o >>= 1) acc += __shfl_down_sync(0xffffffffu, acc, o);
    __shared__ float swsum[8];
    if ((j & 31) == 0) swsum[j >> 5] = acc;
    __syncthreads();
    if (j < 8) {
        float v = swsum[j];
        v += __shfl_down_sync(0xffu, v, 4);
        v += __shfl_down_sync(0xffu, v, 2);
        v += __shfl_down_sync(0xffu, v, 1);
        if (j == 0) g_partials[bb] = v;
    }
}

__global__ void kf_reduce(float* __restrict__ out, int B, int T) {
    __shared__ float s[256];
    float v = 0.f;
    for (int i = threadIdx.x; i < B; i += blockDim.x) v += g_partials[i];
    s[threadIdx.x] = v;
    __syncthreads();
    for (int o = 128; o; o >>= 1) {
        if (threadIdx.x < o) s[threadIdx.x] += s[threadIdx.x + o];
        __syncthreads();
    }
    if (threadIdx.x == 0)
        out[0] = s[0] / ((float)B * (float)(T - 1) * 2.f);
}

extern "C" void kernel_launch(void* const* d_in, const int* in_sizes, int n_in,
                              void* d_out, int out_size) {
    // metadata order: pred_vel, targ_vel, q_pos, q_vel, r_vel, p0
    const float* pred  = (const float*)d_in[0];
    const float* targ  = (const float*)d_in[1];
    const float* q_vel = (const float*)d_in[3];
    const float* r_vel = (const float*)d_in[4];
    int B = in_sizes[5] / 2;          // p0 is (B, 2)
    int T = in_sizes[0] / (B * 2);    // pred_vel is (B, T, 2)

    if (T == 4096 && B >= 1 && B <= 4096) {
        kf_row<<<B, 256>>>(pred, targ, q_vel, r_vel, (float*)d_out, B);
    } else {
        kf_setup<<<1, 256>>>(q_vel, r_vel, T);
        size_t sh = (size_t)T * sizeof(float2);
        kf_main<<<B, 256, sh>>>(pred, targ, T);
        kf_reduce<<<1, 256>>>((float*)d_out, B, T);
    }
}

// round 14
// speedup vs baseline: 1.1546x; 1.1546x over previous
#include <cuda_runtime.h>

#define DT 0.005f

// ---------------- scratch (no allocation allowed) ----------------
__device__ float    g_partials[4096];
__device__ unsigned g_sem = 0;
__device__ float4   g_coef[8192];   // fallback path only

// fallback float2 swizzle
__device__ __forceinline__ int swz(int t)  { return t ^ ((t >> 4) & 15); }
// float4 swizzle (within any 512-aligned region; also valid within 32)
__device__ __forceinline__ int swz4(int s) { return s ^ ((s >> 3) & 7); }

__device__ __forceinline__ void cp16(unsigned dst, const void* src) {
    asm volatile("cp.async.cg.shared.global [%0], [%1], 16;\n" :: "r"(dst), "l"(src));
}
__device__ __forceinline__ void cp_commit() { asm volatile("cp.async.commit_group;\n"); }
template <int N>
__device__ __forceinline__ void cp_wait() { asm volatile("cp.async.wait_group %0;\n" :: "n"(N)); }

// ============================================================================
// Split-row kernel with intra-CTA sub-tile pipelining. Grid 2B=1024 (the
// measured optimum), 128 thr. Each CTA's 2048 steps are processed as TWO
// 1024-step sub-tiles with EXACT scan carry (fold of warp partials):
//   g0 = sub-tile0 pred (+halo)   -> compute starts ~1us earlier
//   g1 = sub-tile1 pred           -> transfer overlaps sub-tile0 compute
//   g2 = first half of targ (8KB) -> halves the tail targ burst
// Pass2-free algebra (R10/R11): pass1 writes Ploc = kp*z + dkp*v_loc in
// place; pass3 rebuilds P = Ploc + dkp*g^(2*(j&3)) * ve. Transient t<64
// exact via gain table (threads j<8, half0, sub-tile0).
// smem ~27.7KB, regs<=64 -> 8 CTAs/SM, 1184 slots >= 1024 -> single wave.
// ============================================================================
__global__ void __launch_bounds__(128, 8)
kf_split(const float* __restrict__ pred, const float* __restrict__ targ,
         const float* __restrict__ qv_p, const float* __restrict__ r_p,
         float* __restrict__ out, int B)
{
    constexpr int NT    = 128;
    constexpr int CHUNK = 8;             // steps per thread per sub-tile
    constexpr int SUB   = 512;           // pairs per sub-tile (1024 steps)
    constexpr int NPREF = 32;            // halo pairs (64 timesteps)
    constexpr int TTR   = 64;            // transient gain length
    constexpr int NTC   = TTR / CHUNK;   // 8 transient chunks

    __shared__ float4 sz[2 * SUB + NPREF];  // [0,512) S0, [512,1024) S1, halo
    __shared__ float4 st4[SUB];             // targ pairs [0,512) (linear)
    __shared__ float4 s_tc[TTR];            // transient (g, kv, u, inv)
    __shared__ float2 s_tb[NTC];            // per-chunk b-affine (Gb, Hb)
    __shared__ float2 s_ve[2 * NT];         // per-chunk entry v (both subtiles)
    __shared__ float2 s_vinit;              // halo-derived entry v (half 1)
    __shared__ float2 s_vnext;              // exact carry: v at end of S0
    __shared__ float  sWG[4], sWBx[4], sWBy[4];
    __shared__ float  sred[4];
    __shared__ int    s_last;

    const int j    = threadIdx.x;
    const int blk  = blockIdx.x;
    const int row  = blk >> 1;
    const int half = blk & 1;
    const int lane = j & 31;
    const int wrp  = j >> 5;

    const float qv = __ldg(qv_p);
    const float r  = __ldg(r_p);

    const unsigned sa = (unsigned)__cvta_generic_to_shared(sz);
    const unsigned ta = (unsigned)__cvta_generic_to_shared(st4);

    // ---- cp.async: g0 = S0 (+halo), g1 = S1, g2 = targ[0,512) ----
    const float4* gp4 = (const float4*)pred + (size_t)row * 2048
                      + (size_t)half * 1024;
    #pragma unroll
    for (int k = 0; k < 4; ++k) {
        int l = j + k * NT;
        cp16(sa + 16u * (unsigned)swz4(l), gp4 + l);
    }
    if (half == 1 && j < NPREF)             // halo = global pairs [-32,0)
        cp16(sa + 16u * (unsigned)(2 * SUB + swz4(j)), gp4 - NPREF + j);
    cp_commit();                             // group 0
    #pragma unroll
    for (int k = 0; k < 4; ++k) {
        int l = j + k * NT;
        cp16(sa + 16u * (unsigned)(SUB + swz4(l)), gp4 + SUB + l);
    }
    cp_commit();                             // group 1
    const float4* gt4 = (const float4*)targ + (size_t)row * 2048
                      + (size_t)half * 1024;
    #pragma unroll
    for (int k = 0; k < 4; ++k) {
        int l = j + k * NT;
        cp16(ta + 16u * (unsigned)l, gt4 + l);
    }
    cp_commit();                             // group 2

    // ---- steady-state constants, per-thread ----
    const float cstar = 0.5f * (sqrtf(fmaf(qv, qv, 4.f * r * qv)) - qv);
    const float cps   = cstar + qv;
    const float invs  = 1.0f / (cps + r);
    const float kvs   = cps * invs;
    const float gs    = 1.0f - kvs;
    const float us    = DT * cstar * invs;
    const float kps   = us / kvs;            // kp* = u*/(1-g*)
    const float dkp   = DT - kps;
    const float gg2 = gs * gs, gg4 = gg2 * gg2;
    const float gg8 = gg4 * gg4;             // g^CHUNK

    // ---- transient gain table + per-chunk b-affine (half 0, j<8) ----
    if (half == 0 && j < NTC) {
        const float r64   = 64.f * r;
        const float rqv64 = 64.f * r * qv;
        const float qvr   = qv + r;
        const float qvr64 = 64.f * qvr;
        const int tstart  = j * CHUNK;
        float p = 1.f, q = 1.f;               // c0 = 1
        #pragma unroll 1
        for (int s = 0; s < tstart; ++s) {
            float pn = fmaf(r64, p, rqv64 * q);
            float qn = fmaf(qvr64, q, 64.f * p);
            p = pn; q = qn;
        }
        float Gb = 1.f, Hb = 0.f;             // b' = g*b + r*u
        #pragma unroll 1
        for (int i = 0; i < CHUNK; ++i) {
            float num  = fmaf(qv,  q, p);
            float den  = fmaf(qvr, q, p);
            float invd = 1.0f / den;
            float kv   = num * invd;
            float inv  = q * invd;
            float u    = DT * p * invd;
            float g    = 1.0f - kv;
            s_tc[tstart + i] = make_float4(g, kv, u, inv);
            Hb = fmaf(g, Hb, r * u);
            Gb *= g;
            float pn = fmaf(r64, p, rqv64 * q);
            float qn = fmaf(qvr64, q, 64.f * p);
            p = pn; q = qn;
        }
        s_tb[j] = make_float2(Gb, Hb);
    }

    cp_wait<2>();                             // g0 landed (g1, g2 in flight)
    __syncthreads();                          // [A0]

    // ---- half 1: parallel halo dot product on warp 0 ----
    if (half == 1 && wrp == 0) {
        float lg = log2f(gs);
        float e0 = (float)(63 - 2 * lane);
        float w0h = kvs * exp2f(e0 * lg);
        float w1h = kvs * exp2f((e0 - 1.f) * lg);
        float4 Z = sz[2 * SUB + swz4(lane)];
        float hx = fmaf(w0h, Z.x, w1h * Z.z);
        float hy = fmaf(w0h, Z.y, w1h * Z.w);
        #pragma unroll
        for (int o = 16; o; o >>= 1) {
            hx += __shfl_down_sync(0xffffffffu, hx, o);
            hy += __shfl_down_sync(0xffffffffu, hy, o);
        }
        if (lane == 0) s_vinit = make_float2(hx, hy);
    }

    float acc = 0.f;

    #pragma unroll
    for (int st = 0; st < 2; ++st) {
        if (st == 1) {
            cp_wait<1>();                     // g1 landed
            __syncthreads();                  // [A1] also guards sW reuse
        }
        const int  base  = st * SUB;
        const bool trans = (half == 0) && (st == 0) && (j < NTC);
        const int  p0 = 4 * j;                // local pair of my chunk

        // ---- pass 1: local v-affine; steady threads emit Ploc in place ----
        float G, Bx = 0.f, By = 0.f;
        if (trans) {
            G = 1.f;
            const int t0 = j * CHUNK;
            #pragma unroll
            for (int i = 0; i < 4; ++i) {
                float4 Z  = sz[base + swz4(p0 + i)];
                float4 c0 = s_tc[t0 + 2 * i];
                float4 c1 = s_tc[t0 + 2 * i + 1];
                Bx = fmaf(c0.x, Bx, c0.y * Z.x);
                By = fmaf(c0.x, By, c0.y * Z.y);
                Bx = fmaf(c1.x, Bx, c1.y * Z.z);
                By = fmaf(c1.x, By, c1.y * Z.w);
                G *= c0.x * c1.x;
            }
        } else {
            G = gg8;
            #pragma unroll
            for (int i = 0; i < 4; ++i) {
                float4 Z = sz[base + swz4(p0 + i)];
                float P0x = fmaf(kps, Z.x, dkp * Bx);   // v_loc BEFORE step
                float P0y = fmaf(kps, Z.y, dkp * By);
                Bx = fmaf(gs, Bx, kvs * Z.x);
                By = fmaf(gs, By, kvs * Z.y);
                float P1x = fmaf(kps, Z.z, dkp * Bx);
                float P1y = fmaf(kps, Z.w, dkp * By);
                Bx = fmaf(gs, Bx, kvs * Z.z);
                By = fmaf(gs, By, kvs * Z.w);
                sz[base + swz4(p0 + i)] = make_float4(P0x, P0y, P1x, P1y);
            }
        }

        // ---- 3-component scan: intra-warp inclusive + warp fold ----
        #pragma unroll
        for (int off = 1; off < 32; off <<= 1) {
            float pG  = __shfl_up_sync(0xffffffffu, G,  off);
            float pBx = __shfl_up_sync(0xffffffffu, Bx, off);
            float pBy = __shfl_up_sync(0xffffffffu, By, off);
            if (lane >= off) {
                Bx = fmaf(G, pBx, Bx);
                By = fmaf(G, pBy, By);
                G *= pG;
            }
        }
        float eG  = __shfl_up_sync(0xffffffffu, G,  1);
        float eBx = __shfl_up_sync(0xffffffffu, Bx, 1);
        float eBy = __shfl_up_sync(0xffffffffu, By, 1);
        if (lane == 0) { eG = 1.f; eBx = 0.f; eBy = 0.f; }
        if (lane == 31) { sWG[wrp] = G; sWBx[wrp] = Bx; sWBy[wrp] = By; }
        __syncthreads();                      // [B_st] partials (+vinit/vnext)

        // entry v of this sub-tile
        float vinx, viny;
        if (st == 0) {
            if (half == 0) { vinx = 0.f; viny = 0.f; }
            else           { float2 vi = s_vinit; vinx = vi.x; viny = vi.y; }
        } else {
            float2 vn = s_vnext; vinx = vn.x; viny = vn.y;
        }

        float Gp = 1.f, Bpx = 0.f, Bpy = 0.f;
        #pragma unroll
        for (int k = 0; k < 3; ++k) {
            if (k < wrp) {
                Bpx = fmaf(sWG[k], Bpx, sWBx[k]);
                Bpy = fmaf(sWG[k], Bpy, sWBy[k]);
                Gp *= sWG[k];
            }
        }
        float Ge = eG * Gp;
        float vx = fmaf(Ge, vinx, fmaf(eG, Bpx, eBx));  // v at chunk entry
        float vy = fmaf(Ge, viny, fmaf(eG, Bpy, eBy));

        // exact carry S0 -> S1 (thread 0 folds all 4 warp totals)
        if (st == 0 && j == 0) {
            float Gt = 1.f, Bxt = 0.f, Byt = 0.f;
            #pragma unroll
            for (int k = 0; k < 4; ++k) {
                Bxt = fmaf(sWG[k], Bxt, sWBx[k]);
                Byt = fmaf(sWG[k], Byt, sWBy[k]);
                Gt *= sWG[k];
            }
            s_vnext = make_float2(fmaf(Gt, vinx, Bxt), fmaf(Gt, viny, Byt));
        }

        // ---- publish entry state; transient does exact replay (writes P) ----
        if (trans) {
            s_ve[j] = make_float2(0.f, 0.f);
            float b = 0.f;
            #pragma unroll
            for (int k = 0; k < NTC - 1; ++k) {
                if (k < j) { float2 tb = s_tb[k]; b = fmaf(tb.x, b, tb.y); }
            }
            const int t0 = j * CHUNK;
            #pragma unroll 1
            for (int i = 0; i < 4; ++i) {
                float4 Z  = sz[base + swz4(p0 + i)];
                float4 c0 = s_tc[t0 + 2 * i];
                float4 c1 = s_tc[t0 + 2 * i + 1];
                float kp0 = fmaf(b, c0.w, c0.z);  b = r * kp0;
                float dx0 = Z.x - vx, dy0 = Z.y - vy;
                float Px0 = fmaf(kp0, dx0, DT * vx);
                float Py0 = fmaf(kp0, dy0, DT * vy);
                vx = fmaf(c0.y, dx0, vx); vy = fmaf(c0.y, dy0, vy);
                float kp1 = fmaf(b, c1.w, c1.z);  b = r * kp1;
                float dx1 = Z.z - vx, dy1 = Z.w - vy;
                float Px1 = fmaf(kp1, dx1, DT * vx);
                float Py1 = fmaf(kp1, dy1, DT * vy);
                vx = fmaf(c1.y, dx1, vx); vy = fmaf(c1.y, dy1, vy);
                sz[base + swz4(p0 + i)] = make_float4(Px0, Py0, Px1, Py1);
            }
        } else {
            s_ve[st * NT + j] = make_float2(vx, vy);
        }
    }

    cp_wait<0>();                             // g2 (targ first half) landed
    __syncthreads();                          // [C] P/Ploc + ve + targ ready

    // ---- pass 3: P = Ploc + w*ve; loss; targ k<4 smem / k>=4 gmem ----
    const int   lpi = j & 3;                  // k-invariant local pair index
    float gpow = 1.f;
    if (lpi == 1) gpow = gg2;
    else if (lpi == 2) gpow = gg4;
    else if (lpi == 3) gpow = gg4 * gg2;
    const float w0 = dkp * gpow;
    const float w1 = w0 * gs;
    #pragma unroll
    for (int k = 0; k < 8; ++k) {
        int m = j + k * NT;
        float4 W = (k < 4) ? st4[m] : gt4[m];
        float4 P = (k < 4) ? sz[swz4(m)] : sz[SUB + swz4(m - SUB)];
        float2 ve = s_ve[(k >> 2) * NT + (j >> 2) + 32 * (k & 3)];
        float Px0 = fmaf(w0, ve.x, P.x);
        float Py0 = fmaf(w0, ve.y, P.y);
        float Px1 = fmaf(w1, ve.x, P.z);
        float Py1 = fmaf(w1, ve.y, P.w);
        if (half != 0 || m != 0) {            // t = 0 has no loss term
            float ex = fmaf(-DT, W.x, Px0);
            float ey = fmaf(-DT, W.y, Py0);
            acc = fmaf(ex, ex, fmaf(ey, ey, acc));
        }
        float ex1 = fmaf(-DT, W.z, Px1);
        float ey1 = fmaf(-DT, W.w, Py1);
        acc = fmaf(ex1, ex1, fmaf(ey1, ey1, acc));
    }

    // ---- block reduce -> partial ----
    #pragma unroll
    for (int o = 16; o; o >>= 1) acc += __shfl_down_sync(0xffffffffu, acc, o);
    if (lane == 0) sred[wrp] = acc;
    __syncthreads();
    if (j == 0) {
        float v = sred[0] + sred[1] + sred[2] + sred[3];
        g_partials[blk] = v;
        __threadfence();
        unsigned done = atomicAdd(&g_sem, 1u);
        s_last = (done == (unsigned)gridDim.x - 1u);
    }
    __syncthreads();

    // ---- last CTA: deterministic final reduction + semaphore reset ----
    if (s_last) {
        __threadfence();
        float* sf = (float*)s_tc;             // reuse table region (done)
        const int nblk = 2 * B;
        float v = 0.f;
        for (int i = j; i < nblk; i += NT) v += g_partials[i];
        sf[j] = v;
        __syncthreads();
        for (int o = 64; o; o >>= 1) {
            if (j < o) sf[j] += sf[j + o];
            __syncthreads();
        }
        if (j == 0) {
            out[0] = sf[0] / ((float)B * 4095.0f * 2.f);
            atomicExch(&g_sem, 0u);
        }
    }
}

// ============================================================================
// Fallback path (any T) — proven Round-1 kernels
// ============================================================================
__global__ void kf_setup(const float* __restrict__ q_vel_p,
                         const float* __restrict__ r_vel_p, int T) {
    __shared__ float skp[4096];
    __shared__ float skv[4096];
    __shared__ int   s_conv;
    __shared__ float s_kp_last, s_kv_last;

    int Tser = T < 4096 ? T : 4096;
    if (threadIdx.x == 0) {
        float qvv = *q_vel_p;
        float rr  = *r_vel_p;
        float bb = 0.f, cc = 1.f;
        float kp = 0.f, kv = 0.f;
        int tconv = Tser;
        for (int t = 0; t < Tser; ++t) {
            float cp  = cc + qvv;
            float bp  = fmaf(DT, cc, bb);
            float S   = cp + rr;
            float inv = __fdividef(1.f, S);
            kv = cp * inv;
            kp = bp * inv;
            skp[t] = kp; skv[t] = kv;
            float rs = rr * inv;
            float nc = cp * rs;
            float nb = bp * rs;
            if (nc == cc && nb == bb) { tconv = t + 1; break; }
            cc = nc; bb = nb;
        }
        s_conv = tconv; s_kp_last = kp; s_kv_last = kv;
    }
    __syncthreads();
    int   tconv = s_conv;
    float kpl = s_kp_last, kvl = s_kv_last;
    for (int t = threadIdx.x; t < T; t += blockDim.x) {
        float kp = (t < tconv) ? skp[t] : kpl;
        float kv = (t < tconv) ? skv[t] : kvl;
        g_coef[t] = make_float4(1.f - kv, kv, DT - kp, kp);
    }
}

__global__ void __launch_bounds__(256)
kf_main(const float* __restrict__ pred, const float* __restrict__ targ, int T) {
    extern __shared__ float2 sp2[];
    const int NT = 256;
    int j = threadIdx.x, bb = blockIdx.x;

    const float4* gp = (const float4*)(pred + (size_t)bb * T * 2);
    int n4 = (T * 2) / 4;
    for (int m = j; m < n4; m += NT) {
        float4 v = gp[m];
        sp2[swz(2 * m)]     = make_float2(v.x, v.y);
        sp2[swz(2 * m + 1)] = make_float2(v.z, v.w);
    }
    __syncthreads();

    int chunk = (T + NT - 1) / NT;
    int t0 = j * chunk;

    float A = 1.f, Bx = 0.f, By = 0.f;
    for (int i = 0; i < chunk; ++i) {
        int t = t0 + i;
        if (t >= T) break;
        float4 cf = g_coef[t];
        float2 z  = sp2[swz(t)];
        A  = A * cf.x;
        Bx = fmaf(cf.x, Bx, cf.y * z.x);
        By = fmaf(cf.x, By, cf.y * z.y);
    }

    __shared__ float sA[256], sBx[256], sBy[256];
    sA[j] = A; sBx[j] = Bx; sBy[j] = By;
    __syncthreads();
    for (int off = 1; off < NT; off <<= 1) {
        float a2 = 0.f, bx2 = 0.f, by2 = 0.f;
        bool act = (j >= off);
        if (act) {
            float ap = sA[j - off], bxp = sBx[j - off], byp = sBy[j - off];
            a2  = A * ap;
            bx2 = fmaf(A, bxp, Bx);
            by2 = fmaf(A, byp, By);
        }
        __syncthreads();
        if (act) { A = a2; Bx = bx2; By = by2; sA[j] = A; sBx[j] = Bx; sBy[j] = By; }
        __syncthreads();
    }
    float vx = (j == 0) ? 0.f : sBx[j - 1];
    float vy = (j == 0) ? 0.f : sBy[j - 1];

    const float2* gt2 = (const float2*)(targ + (size_t)bb * T * 2);
    float acc = 0.f;
    for (int i = 0; i < chunk; ++i) {
        int t = t0 + i;
        if (t >= T) break;
        float4 cf = g_coef[t];
        float2 z  = sp2[swz(t)];
        if (t > 0) {
            float2 w = gt2[t];
            float ex = fmaf(cf.z, vx, fmaf(cf.w, z.x, -DT * w.x));
            float ey = fmaf(cf.z, vy, fmaf(cf.w, z.y, -DT * w.y));
            acc = fmaf(ex, ex, fmaf(ey, ey, acc));
        }
        vx = fmaf(cf.x, vx, cf.y * z.x);
        vy = fmaf(cf.x, vy, cf.y * z.y);
    }

    for (int o = 16; o; o >>= 1) acc += __shfl_down_sync(0xffffffffu, acc, o);
    __shared__ float swsum[8];
    if ((j & 31) == 0) swsum[j >> 5] = acc;
    __syncthreads();
    if (j < 8) {
        float v = swsum[j];
        v += __shfl_down_sync(0xffu, v, 4);
        v += __shfl_down_sync(0xffu, v, 2);
        v += __shfl_down_sync(0xffu, v, 1);
        if (j == 0) g_partials[bb] = v;
    }
}

__global__ void kf_reduce(float* __restrict__ out, int B, int T) {
    __shared__ float s[256];
    float v = 0.f;
    for (int i = threadIdx.x; i < B; i += blockDim.x) v += g_partials[i];
    s[threadIdx.x] = v;
    __syncthreads();
    for (int o = 128; o; o >>= 1) {
        if (threadIdx.x < o) s[threadIdx.x] += s[threadIdx.x + o];
        __syncthreads();
    }
    if (threadIdx.x == 0)
        out[0] = s[0] / ((float)B * (float)(T - 1) * 2.f);
}

extern "C" void kernel_launch(void* const* d_in, const int* in_sizes, int n_in,
                              void* d_out, int out_size) {
    // metadata order: pred_vel, targ_vel, q_pos, q_vel, r_vel, p0
    const float* pred  = (const float*)d_in[0];
    const float* targ  = (const float*)d_in[1];
    const float* q_vel = (const float*)d_in[3];
    const float* r_vel = (const float*)d_in[4];
    int B = in_sizes[5] / 2;          // p0 is (B, 2)
    int T = in_sizes[0] / (B * 2);    // pred_vel is (B, T, 2)

    if (T == 4096 && B >= 1 && B <= 2048) {
        kf_split<<<2 * B, 128>>>(pred, targ, q_vel, r_vel, (float*)d_out, B);
    } else {
        kf_setup<<<1, 256>>>(q_vel, r_vel, T);
        size_t sh = (size_t)T * sizeof(float2);
        kf_main<<<B, 256, sh>>>(pred, targ, T);
        kf_reduce<<<1, 256>>>((float*)d_out, B, T);
    }
}

// round 15
// speedup vs baseline: 1.1575x; 1.0025x over previous
#include <cuda_runtime.h>

#define DT 0.005f

// ---------------- scratch (no allocation allowed) ----------------
__device__ float    g_partials[4096];
__device__ unsigned g_sem = 0;
__device__ float4   g_coef[8192];   // fallback path only

// fallback float2 swizzle
__device__ __forceinline__ int swz(int t)  { return t ^ ((t >> 4) & 15); }
// float4 swizzle
__device__ __forceinline__ int swz4(int s) { return s ^ ((s >> 3) & 7); }

__device__ __forceinline__ void cp16(unsigned dst, const void* src) {
    asm volatile("cp.async.cg.shared.global [%0], [%1], 16;\n" :: "r"(dst), "l"(src));
}
__device__ __forceinline__ void cp_commit() { asm volatile("cp.async.commit_group;\n"); }
template <int N>
__device__ __forceinline__ void cp_wait() { asm volatile("cp.async.wait_group %0;\n" :: "n"(N)); }

// ============================================================================
// Split-row kernel, 3-barrier main path. Grid 2B=1024 (measured optimum),
// 128 thr. The CTA's 2048 steps = two 1024-step sub-tiles whose pass1+scan
// run back-to-back between ONE [A] and ONE [B] barrier (2x LDS/FMA ILP);
// the exact S0->S1 carry is folded locally by every thread from the S0 warp
// partials (no extra sync). Pass2-free algebra (R10+): pass1 writes
// Ploc = kp*z + dkp*v_loc in place; pass3 P = Ploc + dkp*g^(2*(j&3)) * ve.
//   g0 = S0 pred (+halo), g1 = S1 pred, g2 = targ first half (8KB)
// Transient t<64 exact via gain table (threads j<8 of half 0).
// smem ~26.5KB, regs<=73 -> 7 CTAs/SM, 1036 slots >= 1024 -> single wave.
// ============================================================================
__global__ void __launch_bounds__(128, 7)
kf_split(const float* __restrict__ pred, const float* __restrict__ targ,
         const float* __restrict__ qv_p, const float* __restrict__ r_p,
         float* __restrict__ out, int B)
{
    constexpr int NT    = 128;
    constexpr int CHUNK = 8;             // steps per thread per sub-tile
    constexpr int SUB   = 512;           // pairs per sub-tile (1024 steps)
    constexpr int NPREF = 32;            // halo pairs (64 timesteps)
    constexpr int TTR   = 64;            // transient gain length
    constexpr int NTC   = TTR / CHUNK;   // 8 transient chunks

    __shared__ float4 sz[2 * SUB + NPREF];  // [0,512) S0, [512,1024) S1, halo
    __shared__ float4 st4[SUB];             // targ pairs [0,512) (linear)
    __shared__ float4 s_tc[TTR];            // transient (g, kv, u, inv)
    __shared__ float2 s_tb[NTC];            // per-chunk b-affine (Gb, Hb)
    __shared__ float2 s_ve[2 * NT];         // per-chunk entry v (both subtiles)
    __shared__ float2 s_vinit;              // halo-derived entry v (half 1)
    __shared__ float  sWG[2][4], sWBx[2][4], sWBy[2][4];
    __shared__ float  sred[4];
    __shared__ int    s_last;

    const int j    = threadIdx.x;
    const int blk  = blockIdx.x;
    const int row  = blk >> 1;
    const int half = blk & 1;
    const int lane = j & 31;
    const int wrp  = j >> 5;

    const float qv = __ldg(qv_p);
    const float r  = __ldg(r_p);

    const unsigned sa = (unsigned)__cvta_generic_to_shared(sz);
    const unsigned ta = (unsigned)__cvta_generic_to_shared(st4);

    // ---- cp.async: g0 = S0 (+halo), g1 = S1, g2 = targ[0,512) ----
    const float4* gp4 = (const float4*)pred + (size_t)row * 2048
                      + (size_t)half * 1024;
    #pragma unroll
    for (int k = 0; k < 4; ++k) {
        int l = j + k * NT;
        cp16(sa + 16u * (unsigned)swz4(l), gp4 + l);
    }
    if (half == 1 && j < NPREF)             // halo = global pairs [-32,0)
        cp16(sa + 16u * (unsigned)(2 * SUB + swz4(j)), gp4 - NPREF + j);
    cp_commit();                             // group 0
    #pragma unroll
    for (int k = 0; k < 4; ++k) {
        int l = j + k * NT;
        cp16(sa + 16u * (unsigned)(SUB + swz4(l)), gp4 + SUB + l);
    }
    cp_commit();                             // group 1
    const float4* gt4 = (const float4*)targ + (size_t)row * 2048
                      + (size_t)half * 1024;
    #pragma unroll
    for (int k = 0; k < 4; ++k) {
        int l = j + k * NT;
        cp16(ta + 16u * (unsigned)l, gt4 + l);
    }
    cp_commit();                             // group 2

    // ---- steady-state constants, per-thread ----
    const float cstar = 0.5f * (sqrtf(fmaf(qv, qv, 4.f * r * qv)) - qv);
    const float cps   = cstar + qv;
    const float invs  = 1.0f / (cps + r);
    const float kvs   = cps * invs;
    const float gs    = 1.0f - kvs;
    const float us    = DT * cstar * invs;
    const float kps   = us / kvs;            // kp* = u*/(1-g*)
    const float dkp   = DT - kps;
    const float gg2 = gs * gs, gg4 = gg2 * gg2;
    const float gg8 = gg4 * gg4;             // g^CHUNK

    const bool trans = (half == 0) && (j < NTC);

    // ---- transient gain table + per-chunk b-affine (half 0, j<8) ----
    if (trans) {
        const float r64   = 64.f * r;
        const float rqv64 = 64.f * r * qv;
        const float qvr   = qv + r;
        const float qvr64 = 64.f * qvr;
        const int tstart  = j * CHUNK;
        float p = 1.f, q = 1.f;               // c0 = 1
        #pragma unroll 1
        for (int s = 0; s < tstart; ++s) {
            float pn = fmaf(r64, p, rqv64 * q);
            float qn = fmaf(qvr64, q, 64.f * p);
            p = pn; q = qn;
        }
        float Gb = 1.f, Hb = 0.f;             // b' = g*b + r*u
        #pragma unroll 1
        for (int i = 0; i < CHUNK; ++i) {
            float num  = fmaf(qv,  q, p);
            float den  = fmaf(qvr, q, p);
            float invd = 1.0f / den;
            float kv   = num * invd;
            float inv  = q * invd;
            float u    = DT * p * invd;
            float g    = 1.0f - kv;
            s_tc[tstart + i] = make_float4(g, kv, u, inv);
            Hb = fmaf(g, Hb, r * u);
            Gb *= g;
            float pn = fmaf(r64, p, rqv64 * q);
            float qn = fmaf(qvr64, q, 64.f * p);
            p = pn; q = qn;
        }
        s_tb[j] = make_float2(Gb, Hb);
    }

    cp_wait<1>();                             // g0 + g1 landed (g2 in flight)
    __syncthreads();                          // [A]

    // ---- half 1: parallel halo dot product on warp 0 ----
    if (half == 1 && wrp == 0) {
        float lg = log2f(gs);
        float e0 = (float)(63 - 2 * lane);
        float w0h = kvs * exp2f(e0 * lg);
        float w1h = kvs * exp2f((e0 - 1.f) * lg);
        float4 Z = sz[2 * SUB + swz4(lane)];
        float hx = fmaf(w0h, Z.x, w1h * Z.z);
        float hy = fmaf(w0h, Z.y, w1h * Z.w);
        #pragma unroll
        for (int o = 16; o; o >>= 1) {
            hx += __shfl_down_sync(0xffffffffu, hx, o);
            hy += __shfl_down_sync(0xffffffffu, hy, o);
        }
        if (lane == 0) s_vinit = make_float2(hx, hy);
    }

    const int p0 = 4 * j;                     // first local pair of my chunk

    // ---- pass 1, sub-tile 0 (table for transient threads) ----
    float G0, Bx0 = 0.f, By0 = 0.f;
    if (trans) {
        G0 = 1.f;
        const int t0 = j * CHUNK;
        #pragma unroll
        for (int i = 0; i < 4; ++i) {
            float4 Z  = sz[swz4(p0 + i)];
            float4 c0 = s_tc[t0 + 2 * i];
            float4 c1 = s_tc[t0 + 2 * i + 1];
            Bx0 = fmaf(c0.x, Bx0, c0.y * Z.x);
            By0 = fmaf(c0.x, By0, c0.y * Z.y);
            Bx0 = fmaf(c1.x, Bx0, c1.y * Z.z);
            By0 = fmaf(c1.x, By0, c1.y * Z.w);
            G0 *= c0.x * c1.x;
        }
    } else {
        G0 = gg8;
        #pragma unroll
        for (int i = 0; i < 4; ++i) {
            float4 Z = sz[swz4(p0 + i)];
            float P0x = fmaf(kps, Z.x, dkp * Bx0);   // v_loc BEFORE step
            float P0y = fmaf(kps, Z.y, dkp * By0);
            Bx0 = fmaf(gs, Bx0, kvs * Z.x);
            By0 = fmaf(gs, By0, kvs * Z.y);
            float P1x = fmaf(kps, Z.z, dkp * Bx0);
            float P1y = fmaf(kps, Z.w, dkp * By0);
            Bx0 = fmaf(gs, Bx0, kvs * Z.z);
            By0 = fmaf(gs, By0, kvs * Z.w);
            sz[swz4(p0 + i)] = make_float4(P0x, P0y, P1x, P1y);
        }
    }

    // ---- pass 1, sub-tile 1 (always steady) ----
    float G1 = gg8, Bx1 = 0.f, By1 = 0.f;
    #pragma unroll
    for (int i = 0; i < 4; ++i) {
        float4 Z = sz[SUB + swz4(p0 + i)];
        float P0x = fmaf(kps, Z.x, dkp * Bx1);
        float P0y = fmaf(kps, Z.y, dkp * By1);
        Bx1 = fmaf(gs, Bx1, kvs * Z.x);
        By1 = fmaf(gs, By1, kvs * Z.y);
        float P1x = fmaf(kps, Z.z, dkp * Bx1);
        float P1y = fmaf(kps, Z.w, dkp * By1);
        Bx1 = fmaf(gs, Bx1, kvs * Z.z);
        By1 = fmaf(gs, By1, kvs * Z.w);
        sz[SUB + swz4(p0 + i)] = make_float4(P0x, P0y, P1x, P1y);
    }

    // ---- intra-warp scans for both sub-tiles (interleaved ILP) ----
    #pragma unroll
    for (int off = 1; off < 32; off <<= 1) {
        float pG0  = __shfl_up_sync(0xffffffffu, G0,  off);
        float pBx0 = __shfl_up_sync(0xffffffffu, Bx0, off);
        float pBy0 = __shfl_up_sync(0xffffffffu, By0, off);
        float pG1  = __shfl_up_sync(0xffffffffu, G1,  off);
        float pBx1 = __shfl_up_sync(0xffffffffu, Bx1, off);
        float pBy1 = __shfl_up_sync(0xffffffffu, By1, off);
        if (lane >= off) {
            Bx0 = fmaf(G0, pBx0, Bx0);
            By0 = fmaf(G0, pBy0, By0);
            G0 *= pG0;
            Bx1 = fmaf(G1, pBx1, Bx1);
            By1 = fmaf(G1, pBy1, By1);
            G1 *= pG1;
        }
    }
    float eG0  = __shfl_up_sync(0xffffffffu, G0,  1);
    float eBx0 = __shfl_up_sync(0xffffffffu, Bx0, 1);
    float eBy0 = __shfl_up_sync(0xffffffffu, By0, 1);
    float eG1  = __shfl_up_sync(0xffffffffu, G1,  1);
    float eBx1 = __shfl_up_sync(0xffffffffu, Bx1, 1);
    float eBy1 = __shfl_up_sync(0xffffffffu, By1, 1);
    if (lane == 0) {
        eG0 = 1.f; eBx0 = 0.f; eBy0 = 0.f;
        eG1 = 1.f; eBx1 = 0.f; eBy1 = 0.f;
    }
    if (lane == 31) {
        sWG[0][wrp] = G0; sWBx[0][wrp] = Bx0; sWBy[0][wrp] = By0;
        sWG[1][wrp] = G1; sWBx[1][wrp] = Bx1; sWBy[1][wrp] = By1;
    }
    __syncthreads();                          // [B] partials + vinit ready

    // ---- fold: S0 entry, S0 total -> S1 entry, S1 prefix ----
    float vinx = 0.f, viny = 0.f;
    if (half == 1) { float2 vi = s_vinit; vinx = vi.x; viny = vi.y; }

    float Gp0 = 1.f, Bpx0 = 0.f, Bpy0 = 0.f;
    float Gp1 = 1.f, Bpx1 = 0.f, Bpy1 = 0.f;
    float Gt = 1.f, Bxt = 0.f, Byt = 0.f;
    #pragma unroll
    for (int k = 0; k < 4; ++k) {
        float wg0 = sWG[0][k], wbx0 = sWBx[0][k], wby0 = sWBy[0][k];
        if (k < wrp) {
            Bpx0 = fmaf(wg0, Bpx0, wbx0);
            Bpy0 = fmaf(wg0, Bpy0, wby0);
            Gp0 *= wg0;
            float wg1 = sWG[1][k];
            Bpx1 = fmaf(wg1, Bpx1, sWBx[1][k]);
            Bpy1 = fmaf(wg1, Bpy1, sWBy[1][k]);
            Gp1 *= wg1;
        }
        Bxt = fmaf(wg0, Bxt, wbx0);           // S0 total (all 4 warps)
        Byt = fmaf(wg0, Byt, wby0);
        Gt *= wg0;
    }
    float Ge0 = eG0 * Gp0;
    float vx0 = fmaf(Ge0, vinx, fmaf(eG0, Bpx0, eBx0));  // S0 chunk entry
    float vy0 = fmaf(Ge0, viny, fmaf(eG0, Bpy0, eBy0));
    float ven1x = fmaf(Gt, vinx, Bxt);                   // v at end of S0
    float ven1y = fmaf(Gt, viny, Byt);
    float Ge1 = eG1 * Gp1;
    float vx1 = fmaf(Ge1, ven1x, fmaf(eG1, Bpx1, eBx1)); // S1 chunk entry
    float vy1 = fmaf(Ge1, ven1y, fmaf(eG1, Bpy1, eBy1));

    // ---- publish entry states; transient does exact replay (writes P) ----
    if (trans) {
        s_ve[j] = make_float2(0.f, 0.f);
        float b = 0.f;
        #pragma unroll
        for (int k = 0; k < NTC - 1; ++k) {
            if (k < j) { float2 tb = s_tb[k]; b = fmaf(tb.x, b, tb.y); }
        }
        const int t0 = j * CHUNK;
        float vx = vx0, vy = vy0;
        #pragma unroll 1
        for (int i = 0; i < 4; ++i) {
            float4 Z  = sz[swz4(p0 + i)];
            float4 c0 = s_tc[t0 + 2 * i];
            float4 c1 = s_tc[t0 + 2 * i + 1];
            float kp0 = fmaf(b, c0.w, c0.z);  b = r * kp0;
            float dx0 = Z.x - vx, dy0 = Z.y - vy;
            float Px0 = fmaf(kp0, dx0, DT * vx);
            float Py0 = fmaf(kp0, dy0, DT * vy);
            vx = fmaf(c0.y, dx0, vx); vy = fmaf(c0.y, dy0, vy);
            float kp1 = fmaf(b, c1.w, c1.z);  b = r * kp1;
            float dx1 = Z.z - vx, dy1 = Z.w - vy;
            float Px1 = fmaf(kp1, dx1, DT * vx);
            float Py1 = fmaf(kp1, dy1, DT * vy);
            vx = fmaf(c1.y, dx1, vx); vy = fmaf(c1.y, dy1, vy);
            sz[swz4(p0 + i)] = make_float4(Px0, Py0, Px1, Py1);
        }
    } else {
        s_ve[j] = make_float2(vx0, vy0);
    }
    s_ve[NT + j] = make_float2(vx1, vy1);

    cp_wait<0>();                             // g2 (targ first half) landed
    __syncthreads();                          // [C] P/Ploc + ve + targ ready

    // ---- pass 3: P = Ploc + w*ve; loss; targ k<4 smem / k>=4 gmem ----
    const int   lpi = j & 3;                  // k-invariant local pair index
    float gpow = 1.f;
    if (lpi == 1) gpow = gg2;
    else if (lpi == 2) gpow = gg4;
    else if (lpi == 3) gpow = gg4 * gg2;
    const float w0 = dkp * gpow;
    const float w1 = w0 * gs;
    float acc = 0.f;
    #pragma unroll
    for (int k = 0; k < 8; ++k) {
        int m = j + k * NT;
        float4 W = (k < 4) ? st4[m] : gt4[m];
        float4 P = (k < 4) ? sz[swz4(m)] : sz[SUB + swz4(m - SUB)];
        float2 ve = s_ve[(k >> 2) * NT + (j >> 2) + 32 * (k & 3)];
        float Px0 = fmaf(w0, ve.x, P.x);
        float Py0 = fmaf(w0, ve.y, P.y);
        float Px1 = fmaf(w1, ve.x, P.z);
        float Py1 = fmaf(w1, ve.y, P.w);
        if (half != 0 || m != 0) {            // t = 0 has no loss term
            float ex = fmaf(-DT, W.x, Px0);
            float ey = fmaf(-DT, W.y, Py0);
            acc = fmaf(ex, ex, fmaf(ey, ey, acc));
        }
        float ex1 = fmaf(-DT, W.z, Px1);
        float ey1 = fmaf(-DT, W.w, Py1);
        acc = fmaf(ex1, ex1, fmaf(ey1, ey1, acc));
    }

    // ---- block reduce -> partial ----
    #pragma unroll
    for (int o = 16; o; o >>= 1) acc += __shfl_down_sync(0xffffffffu, acc, o);
    if (lane == 0) sred[wrp] = acc;
    __syncthreads();
    if (j == 0) {
        float v = sred[0] + sred[1] + sred[2] + sred[3];
        g_partials[blk] = v;
        __threadfence();
        unsigned done = atomicAdd(&g_sem, 1u);
        s_last = (done == (unsigned)gridDim.x - 1u);
    }
    __syncthreads();

    // ---- last CTA: deterministic final reduction + semaphore reset ----
    if (s_last) {
        __threadfence();
        float* sf = (float*)s_tc;             // reuse table region (done)
        const int nblk = 2 * B;
        float v = 0.f;
        for (int i = j; i < nblk; i += NT) v += g_partials[i];
        sf[j] = v;
        __syncthreads();
        for (int o = 64; o; o >>= 1) {
            if (j < o) sf[j] += sf[j + o];
            __syncthreads();
        }
        if (j == 0) {
            out[0] = sf[0] / ((float)B * 4095.0f * 2.f);
            atomicExch(&g_sem, 0u);
        }
    }
}

// ============================================================================
// Fallback path (any T) — proven Round-1 kernels
// ============================================================================
__global__ void kf_setup(const float* __restrict__ q_vel_p,
                         const float* __restrict__ r_vel_p, int T) {
    __shared__ float skp[4096];
    __shared__ float skv[4096];
    __shared__ int   s_conv;
    __shared__ float s_kp_last, s_kv_last;

    int Tser = T < 4096 ? T : 4096;
    if (threadIdx.x == 0) {
        float qvv = *q_vel_p;
        float rr  = *r_vel_p;
        float bb = 0.f, cc = 1.f;
        float kp = 0.f, kv = 0.f;
        int tconv = Tser;
        for (int t = 0; t < Tser; ++t) {
            float cp  = cc + qvv;
            float bp  = fmaf(DT, cc, bb);
            float S   = cp + rr;
            float inv = __fdividef(1.f, S);
            kv = cp * inv;
            kp = bp * inv;
            skp[t] = kp; skv[t] = kv;
            float rs = rr * inv;
            float nc = cp * rs;
            float nb = bp * rs;
            if (nc == cc && nb == bb) { tconv = t + 1; break; }
            cc = nc; bb = nb;
        }
        s_conv = tconv; s_kp_last = kp; s_kv_last = kv;
    }
    __syncthreads();
    int   tconv = s_conv;
    float kpl = s_kp_last, kvl = s_kv_last;
    for (int t = threadIdx.x; t < T; t += blockDim.x) {
        float kp = (t < tconv) ? skp[t] : kpl;
        float kv = (t < tconv) ? skv[t] : kvl;
        g_coef[t] = make_float4(1.f - kv, kv, DT - kp, kp);
    }
}

__global__ void __launch_bounds__(256)
kf_main(const float* __restrict__ pred, const float* __restrict__ targ, int T) {
    extern __shared__ float2 sp2[];
    const int NT = 256;
    int j = threadIdx.x, bb = blockIdx.x;

    const float4* gp = (const float4*)(pred + (size_t)bb * T * 2);
    int n4 = (T * 2) / 4;
    for (int m = j; m < n4; m += NT) {
        float4 v = gp[m];
        sp2[swz(2 * m)]     = make_float2(v.x, v.y);
        sp2[swz(2 * m + 1)] = make_float2(v.z, v.w);
    }
    __syncthreads();

    int chunk = (T + NT - 1) / NT;
    int t0 = j * chunk;

    float A = 1.f, Bx = 0.f, By = 0.f;
    for (int i = 0; i < chunk; ++i) {
        int t = t0 + i;
        if (t >= T) break;
        float4 cf = g_coef[t];
        float2 z  = sp2[swz(t)];
        A  = A * cf.x;
        Bx = fmaf(cf.x, Bx, cf.y * z.x);
        By = fmaf(cf.x, By, cf.y * z.y);
    }

    __shared__ float sA[256], sBx[256], sBy[256];
    sA[j] = A; sBx[j] = Bx; sBy[j] = By;
    __syncthreads();
    for (int off = 1; off < NT; off <<= 1) {
        float a2 = 0.f, bx2 = 0.f, by2 = 0.f;
        bool act = (j >= off);
        if (act) {
            float ap = sA[j - off], bxp = sBx[j - off], byp = sBy[j - off];
            a2  = A * ap;
            bx2 = fmaf(A, bxp, Bx);
            by2 = fmaf(A, byp, By);
        }
        __syncthreads();
        if (act) { A = a2; Bx = bx2; By = by2; sA[j] = A; sBx[j] = Bx; sBy[j] = By; }
        __syncthreads();
    }
    float vx = (j == 0) ? 0.f : sBx[j - 1];
    float vy = (j == 0) ? 0.f : sBy[j - 1];

    const float2* gt2 = (const float2*)(targ + (size_t)bb * T * 2);
    float acc = 0.f;
    for (int i = 0; i < chunk; ++i) {
        int t = t0 + i;
        if (t >= T) break;
        float4 cf = g_coef[t];
        float2 z  = sp2[swz(t)];
        if (t > 0) {
            float2 w = gt2[t];
            float ex = fmaf(cf.z, vx, fmaf(cf.w, z.x, -DT * w.x));
            float ey = fmaf(cf.z, vy, fmaf(cf.w, z.y, -DT * w.y));
            acc = fmaf(ex, ex, fmaf(ey, ey, acc));
        }
        vx = fmaf(cf.x, vx, cf.y * z.x);
        vy = fmaf(cf.x, vy, cf.y * z.y);
    }

    for (int o = 16; o; o >>= 1) acc += __shfl_down_sync(0xffffffffu, acc, o);
    __shared__ float swsum[8];
    if ((j & 31) == 0) swsum[j >> 5] = acc;
    __syncthreads();
    if (j < 8) {
        float v = swsum[j];
        v += __shfl_down_sync(0xffu, v, 4);
        v += __shfl_down_sync(0xffu, v, 2);
        v += __shfl_down_sync(0xffu, v, 1);
        if (j == 0) g_partials[bb] = v;
    }
}

__global__ void kf_reduce(float* __restrict__ out, int B, int T) {
    __shared__ float s[256];
    float v = 0.f;
    for (int i = threadIdx.x; i < B; i += blockDim.x) v += g_partials[i];
    s[threadIdx.x] = v;
    __syncthreads();
    for (int o = 128; o; o >>= 1) {
        if (threadIdx.x < o) s[threadIdx.x] += s[threadIdx.x + o];
        __syncthreads();
    }
    if (threadIdx.x == 0)
        out[0] = s[0] / ((float)B * (float)(T - 1) * 2.f);
}

extern "C" void kernel_launch(void* const* d_in, const int* in_sizes, int n_in,
                              void* d_out, int out_size) {
    // metadata order: pred_vel, targ_vel, q_pos, q_vel, r_vel, p0
    const float* pred  = (const float*)d_in[0];
    const float* targ  = (const float*)d_in[1];
    const float* q_vel = (const float*)d_in[3];
    const float* r_vel = (const float*)d_in[4];
    int B = in_sizes[5] / 2;          // p0 is (B, 2)
    int T = in_sizes[0] / (B * 2);    // pred_vel is (B, T, 2)

    if (T == 4096 && B >= 1 && B <= 2048) {
        kf_split<<<2 * B, 128>>>(pred, targ, q_vel, r_vel, (float*)d_out, B);
    } else {
        kf_setup<<<1, 256>>>(q_vel, r_vel, T);
        size_t sh = (size_t)T * sizeof(float2);
        kf_main<<<B, 256, sh>>>(pred, targ, T);
        kf_reduce<<<1, 256>>>((float*)d_out, B, T);
    }
}